// round 1
// baseline (speedup 1.0000x reference)
#include <cuda_runtime.h>
#include <cstdint>
#include <cstddef>

#define N_USER 200000
#define N_NEWS 100000
#define N_SOURCE 5000
#define N_FOLLOWER 200000
#define HDIM 128
#define E_POSTS 500000
#define E_PUB 100000
#define E_FOL 1000000

#define TOT_NODES (N_USER + N_NEWS + N_SOURCE + N_FOLLOWER)

// feature-buffer offsets (in floats)
#define OFF_U ((size_t)0)
#define OFF_N ((size_t)N_USER * HDIM)
#define OFF_S ((size_t)(N_USER + N_NEWS) * HDIM)
#define OFF_F ((size_t)(N_USER + N_NEWS + N_SOURCE) * HDIM)

// degree-array segment offsets (floats)
#define DS_POSTS_U 0        // 200000
#define DS_POSTS_N 200000   // 100000
#define DS_PUB_S   300000   // 5000
#define DS_PUB_N   305000   // 100000
#define DS_FOL_F   405000   // 200000
#define DS_FOL_U   605000   // 200000
#define DEG_TOTAL  805000

// scratch (device globals: allocation-free rule)
__device__ float g_bufA[(size_t)TOT_NODES * HDIM];
__device__ float g_bufB[(size_t)TOT_NODES * HDIM];
__device__ float g_agg[(size_t)N_USER * HDIM];     // max n_dst = 200000
__device__ float g_deg[DEG_TOTAL];

// ---------------------------------------------------------------------------
__global__ void zero_kernel(float* __restrict__ p, size_t n4) {
    size_t i = (size_t)blockIdx.x * blockDim.x + threadIdx.x;
    size_t stride = (size_t)gridDim.x * blockDim.x;
    float4 z = make_float4(0.f, 0.f, 0.f, 0.f);
    float4* p4 = reinterpret_cast<float4*>(p);
    for (; i < n4; i += stride) p4[i] = z;
}

__global__ void count_kernel(const int* __restrict__ idx, int n, float* __restrict__ cnt) {
    int i = blockIdx.x * blockDim.x + threadIdx.x;
    int stride = gridDim.x * blockDim.x;
    for (; i < n; i += stride) atomicAdd(&cnt[idx[i]], 1.0f);
}

__global__ void rsqrt_kernel(float* __restrict__ p, int n) {
    int i = blockIdx.x * blockDim.x + threadIdx.x;
    int stride = gridDim.x * blockDim.x;
    for (; i < n; i += stride) {
        float v = p[i];
        p[i] = rsqrtf(v < 1.0f ? 1.0f : v);
    }
}

// one warp per edge (grid-stride): gather h_src * rsqrt(deg_out), vector-RED into agg[dst]
__global__ void scatter_kernel(const float* __restrict__ h,
                               const int* __restrict__ src,
                               const int* __restrict__ dst,
                               const float* __restrict__ rs_out,
                               float* __restrict__ agg, int E) {
    int warp = (blockIdx.x * blockDim.x + threadIdx.x) >> 5;
    int lane = threadIdx.x & 31;
    int nwarps = (gridDim.x * blockDim.x) >> 5;
    for (int e = warp; e < E; e += nwarps) {
        int s = src[e];
        int d = dst[e];
        float sc = rs_out[s];
        float4 v = *reinterpret_cast<const float4*>(h + (size_t)s * HDIM + lane * 4);
        v.x *= sc; v.y *= sc; v.z *= sc; v.w *= sc;
        float* a = agg + (size_t)d * HDIM + lane * 4;
        asm volatile("red.global.add.v4.f32 [%0], {%1,%2,%3,%4};"
                     :: "l"(a), "f"(v.x), "f"(v.y), "f"(v.z), "f"(v.w) : "memory");
    }
}

// ---------------------------------------------------------------------------
// C[M,128] = epilogue( (rowscale?A*rs:A)[M,K] @ W[K,128] )
// epilogue: t += bias; if(acc) t += C_old; t *= scale; if(act) leaky_relu(t, 0.01)
#define BM 64
#define BK 16
__global__ __launch_bounds__(256) void gemm_kernel(
    const float* __restrict__ A, const float* __restrict__ rowscale,
    const float* __restrict__ W, const float* __restrict__ bias,
    float* __restrict__ C, int M, int K,
    int accumulate, float scale, int do_act) {
    __shared__ float As[BK][BM + 4];
    __shared__ float Ws[BK][HDIM];

    int block_row = blockIdx.x * BM;
    int tid = threadIdx.x;
    int tx = tid & 31;   // col group: cols tx*4 .. tx*4+3
    int ty = tid >> 5;   // row group: rows ty*8 .. ty*8+7

    float acc[8][4];
#pragma unroll
    for (int i = 0; i < 8; i++)
#pragma unroll
        for (int j = 0; j < 4; j++) acc[i][j] = 0.f;

    for (int k0 = 0; k0 < K; k0 += BK) {
        // --- load A tile 64x16 (transposed into As) ---
        {
            int row = tid >> 2;            // 0..63
            int kk = (tid & 3) * 4;        // 0,4,8,12
            float4 v = make_float4(0.f, 0.f, 0.f, 0.f);
            int grow = block_row + row;
            if (grow < M) {
                const float* ap = A + (size_t)grow * K + k0 + kk;
                if (k0 + kk + 3 < K) {
                    v = *reinterpret_cast<const float4*>(ap);
                } else {
                    float t[4];
#pragma unroll
                    for (int j = 0; j < 4; j++)
                        t[j] = (k0 + kk + j < K) ? ap[j] : 0.f;
                    v = make_float4(t[0], t[1], t[2], t[3]);
                }
                if (rowscale) {
                    float s = rowscale[grow];
                    v.x *= s; v.y *= s; v.z *= s; v.w *= s;
                }
            }
            As[kk + 0][row] = v.x;
            As[kk + 1][row] = v.y;
            As[kk + 2][row] = v.z;
            As[kk + 3][row] = v.w;
        }
        // --- load W tile 16x128 ---
        {
#pragma unroll
            for (int j = 0; j < 2; j++) {
                int fi = tid * 2 + j;          // 0..511 float4s
                int kk = fi >> 5;              // 0..15
                int col = (fi & 31) * 4;       // 0..124
                float4 v = make_float4(0.f, 0.f, 0.f, 0.f);
                if (k0 + kk < K)
                    v = *reinterpret_cast<const float4*>(W + (size_t)(k0 + kk) * HDIM + col);
                *reinterpret_cast<float4*>(&Ws[kk][col]) = v;
            }
        }
        __syncthreads();
#pragma unroll
        for (int kk = 0; kk < BK; kk++) {
            float a[8], w[4];
#pragma unroll
            for (int i = 0; i < 8; i++) a[i] = As[kk][ty * 8 + i];
#pragma unroll
            for (int j = 0; j < 4; j++) w[j] = Ws[kk][tx * 4 + j];
#pragma unroll
            for (int i = 0; i < 8; i++)
#pragma unroll
                for (int j = 0; j < 4; j++) acc[i][j] += a[i] * w[j];
        }
        __syncthreads();
    }

    // --- epilogue ---
    int col = tx * 4;
    float b0 = 0.f, b1 = 0.f, b2 = 0.f, b3 = 0.f;
    if (bias) { b0 = bias[col]; b1 = bias[col + 1]; b2 = bias[col + 2]; b3 = bias[col + 3]; }
#pragma unroll
    for (int i = 0; i < 8; i++) {
        int grow = block_row + ty * 8 + i;
        if (grow >= M) continue;
        float4 r = make_float4(acc[i][0] + b0, acc[i][1] + b1, acc[i][2] + b2, acc[i][3] + b3);
        float* cp = C + (size_t)grow * HDIM + col;
        if (accumulate) {
            float4 o = *reinterpret_cast<float4*>(cp);
            r.x += o.x; r.y += o.y; r.z += o.z; r.w += o.w;
        }
        r.x *= scale; r.y *= scale; r.z *= scale; r.w *= scale;
        if (do_act) {
            r.x = r.x > 0.f ? r.x : 0.01f * r.x;
            r.y = r.y > 0.f ? r.y : 0.01f * r.y;
            r.z = r.z > 0.f ? r.z : 0.01f * r.z;
            r.w = r.w > 0.f ? r.w : 0.01f * r.w;
        }
        *reinterpret_cast<float4*>(cp) = r;
    }
}

// final head: out[r,0:2] = h1[r,:] @ Wl[128,2] + bl   (one warp per row)
__global__ void head_kernel(const float* __restrict__ h1, const float* __restrict__ Wl,
                            const float* __restrict__ bl, float* __restrict__ out, int Nrows) {
    int warp = (blockIdx.x * blockDim.x + threadIdx.x) >> 5;
    int lane = threadIdx.x & 31;
    int nwarps = (gridDim.x * blockDim.x) >> 5;
    int k = lane * 4;
    float w00 = Wl[(k + 0) * 2], w01 = Wl[(k + 0) * 2 + 1];
    float w10 = Wl[(k + 1) * 2], w11 = Wl[(k + 1) * 2 + 1];
    float w20 = Wl[(k + 2) * 2], w21 = Wl[(k + 2) * 2 + 1];
    float w30 = Wl[(k + 3) * 2], w31 = Wl[(k + 3) * 2 + 1];
    for (int r = warp; r < Nrows; r += nwarps) {
        float4 v = *reinterpret_cast<const float4*>(h1 + (size_t)r * HDIM + k);
        float p0 = v.x * w00 + v.y * w10 + v.z * w20 + v.w * w30;
        float p1 = v.x * w01 + v.y * w11 + v.z * w21 + v.w * w31;
#pragma unroll
        for (int off = 16; off; off >>= 1) {
            p0 += __shfl_xor_sync(0xffffffffu, p0, off);
            p1 += __shfl_xor_sync(0xffffffffu, p1, off);
        }
        if (lane == 0) {
            out[(size_t)r * 2 + 0] = p0 + bl[0];
            out[(size_t)r * 2 + 1] = p1 + bl[1];
        }
    }
}

// ---------------------------------------------------------------------------
extern "C" void kernel_launch(void* const* d_in, const int* in_sizes, int n_in,
                              void* d_out, int out_size) {
    const float* x_user = (const float*)d_in[0];
    const float* x_news = (const float*)d_in[1];
    const float* x_source = (const float*)d_in[2];
    const float* x_follower = (const float*)d_in[3];
    const float* Wi1_user = (const float*)d_in[4];
    const float* bi1_user = (const float*)d_in[5];
    const float* Wi1_news = (const float*)d_in[6];
    const float* bi1_news = (const float*)d_in[7];
    const float* Wi1_source = (const float*)d_in[8];
    const float* bi1_source = (const float*)d_in[9];
    const float* Wi1_follower = (const float*)d_in[10];
    const float* bi1_follower = (const float*)d_in[11];
    const float* Wi2 = (const float*)d_in[12];
    const float* bi2 = (const float*)d_in[13];
    const float* conv1_W = (const float*)d_in[14];
    const float* conv1_b = (const float*)d_in[15];
    const float* conv2_W = (const float*)d_in[16];
    const float* conv2_b = (const float*)d_in[17];
    const float* Wl_user = (const float*)d_in[18];
    const float* bl_user = (const float*)d_in[19];
    const float* Wl_news = (const float*)d_in[20];
    const float* bl_news = (const float*)d_in[21];
    const float* Wl_source = (const float*)d_in[22];
    const float* bl_source = (const float*)d_in[23];
    const float* Wl_follower = (const float*)d_in[24];
    const float* bl_follower = (const float*)d_in[25];
    const int* posts_u = (const int*)d_in[26];
    const int* posts_n = (const int*)d_in[27];
    const int* pub_s = (const int*)d_in[28];
    const int* pub_n = (const int*)d_in[29];
    const int* fol_f = (const int*)d_in[30];
    const int* fol_u = (const int*)d_in[31];
    float* out = (float*)d_out;

    float *bufA, *bufB, *agg, *deg;
    cudaGetSymbolAddress((void**)&bufA, g_bufA);
    cudaGetSymbolAddress((void**)&bufB, g_bufB);
    cudaGetSymbolAddress((void**)&agg, g_agg);
    cudaGetSymbolAddress((void**)&deg, g_deg);

    auto zero = [](float* p, size_t n) {
        int blocks = (int)((n / 4 + 255) / 256);
        if (blocks > 4096) blocks = 4096;
        zero_kernel<<<blocks, 256>>>(p, n / 4);
    };
    auto gemm = [](const float* A, const float* rs, const float* W, const float* b,
                   float* C, int M, int K, int acc, float scale, int act) {
        gemm_kernel<<<(M + BM - 1) / BM, 256>>>(A, rs, W, b, C, M, K, acc, scale, act);
    };
    auto scatter = [](const float* h, const int* s, const int* d, const float* rs,
                      float* aggp, int E) {
        int blocks = (E + 7) / 8;
        scatter_kernel<<<blocks, 256>>>(h, s, d, rs, aggp, E);
    };

    // ---- degrees ----
    zero(deg, (size_t)DEG_TOTAL);
    count_kernel<<<2048, 256>>>(posts_u, E_POSTS, deg + DS_POSTS_U);
    count_kernel<<<2048, 256>>>(posts_n, E_POSTS, deg + DS_POSTS_N);
    count_kernel<<<512, 256>>>(pub_s, E_PUB, deg + DS_PUB_S);
    count_kernel<<<512, 256>>>(pub_n, E_PUB, deg + DS_PUB_N);
    count_kernel<<<4096, 256>>>(fol_f, E_FOL, deg + DS_FOL_F);
    count_kernel<<<4096, 256>>>(fol_u, E_FOL, deg + DS_FOL_U);
    rsqrt_kernel<<<2048, 256>>>(deg, DEG_TOTAL);

    // ---- dense layer 1: x -> bufA ----
    gemm(x_user, nullptr, Wi1_user, bi1_user, bufA + OFF_U, N_USER, 128, 0, 1.f, 1);
    gemm(x_news, nullptr, Wi1_news, bi1_news, bufA + OFF_N, N_NEWS, 300, 0, 1.f, 1);
    gemm(x_source, nullptr, Wi1_source, bi1_source, bufA + OFF_S, N_SOURCE, 128, 0, 1.f, 1);
    gemm(x_follower, nullptr, Wi1_follower, bi1_follower, bufA + OFF_F, N_FOLLOWER, 128, 0, 1.f, 1);

    // ---- dense layer 2: bufA -> bufB ----
    const size_t HH = (size_t)HDIM * HDIM;
    gemm(bufA + OFF_U, nullptr, Wi2 + 0 * HH, bi2 + 0 * HDIM, bufB + OFF_U, N_USER, 128, 0, 1.f, 1);
    gemm(bufA + OFF_N, nullptr, Wi2 + 1 * HH, bi2 + 1 * HDIM, bufB + OFF_N, N_NEWS, 128, 0, 1.f, 1);
    gemm(bufA + OFF_S, nullptr, Wi2 + 2 * HH, bi2 + 2 * HDIM, bufB + OFF_S, N_SOURCE, 128, 0, 1.f, 1);
    gemm(bufA + OFF_F, nullptr, Wi2 + 3 * HH, bi2 + 3 * HDIM, bufB + OFF_F, N_FOLLOWER, 128, 0, 1.f, 1);

    // relation table
    struct Rel { const int* src; const int* dst; int E; size_t hoff; int rs_out; int rs_in; int n_dst; };
    Rel rel[6] = {
        {posts_u, posts_n, E_POSTS, OFF_U, DS_POSTS_U, DS_POSTS_N, N_NEWS},     // r0 user->news
        {posts_n, posts_u, E_POSTS, OFF_N, DS_POSTS_N, DS_POSTS_U, N_USER},     // r1 news->user
        {pub_s, pub_n, E_PUB, OFF_S, DS_PUB_S, DS_PUB_N, N_NEWS},               // r2 source->news
        {pub_n, pub_s, E_PUB, OFF_N, DS_PUB_N, DS_PUB_S, N_SOURCE},             // r3 news->source
        {fol_f, fol_u, E_FOL, OFF_F, DS_FOL_F, DS_FOL_U, N_USER},               // r4 follower->user
        {fol_u, fol_f, E_FOL, OFF_U, DS_FOL_U, DS_FOL_F, N_FOLLOWER},           // r5 user->follower
    };

    auto run_rel = [&](const float* hbase, int r, int i, const float* Wc, const float* bc,
                       float* outp, int acc, float scale, int act) {
        const Rel& R = rel[r];
        zero(agg, (size_t)R.n_dst * HDIM);
        scatter(hbase + R.hoff, R.src, R.dst, deg + R.rs_out, agg, R.E);
        gemm(agg, deg + R.rs_in, Wc + ((size_t)i * 6 + r) * HH, bc + ((size_t)i * 6 + r) * HDIM,
             outp, R.n_dst, HDIM, acc, scale, act);
    };

    // ---- conv1: bufB -> bufA ----
    run_rel(bufB, 1, 0, conv1_W, conv1_b, bufA + OFF_U, 0, 1.0f, 0);
    run_rel(bufB, 4, 0, conv1_W, conv1_b, bufA + OFF_U, 1, 0.5f, 1);
    run_rel(bufB, 0, 1, conv1_W, conv1_b, bufA + OFF_N, 0, 1.0f, 0);
    run_rel(bufB, 2, 1, conv1_W, conv1_b, bufA + OFF_N, 1, 0.5f, 1);
    run_rel(bufB, 3, 2, conv1_W, conv1_b, bufA + OFF_S, 0, 1.0f, 1);
    run_rel(bufB, 5, 3, conv1_W, conv1_b, bufA + OFF_F, 0, 1.0f, 1);

    // ---- conv2: bufA -> h1 region of d_out ----
    const size_t H1_BASE = (size_t)TOT_NODES * 2;  // 1,010,000
    float* h1_u = out + H1_BASE + OFF_U;
    float* h1_n = out + H1_BASE + OFF_N;
    float* h1_s = out + H1_BASE + OFF_S;
    float* h1_f = out + H1_BASE + OFF_F;
    run_rel(bufA, 1, 0, conv2_W, conv2_b, h1_u, 0, 1.0f, 0);
    run_rel(bufA, 4, 0, conv2_W, conv2_b, h1_u, 1, 0.5f, 1);
    run_rel(bufA, 0, 1, conv2_W, conv2_b, h1_n, 0, 1.0f, 0);
    run_rel(bufA, 2, 1, conv2_W, conv2_b, h1_n, 1, 0.5f, 1);
    run_rel(bufA, 3, 2, conv2_W, conv2_b, h1_s, 0, 1.0f, 1);
    run_rel(bufA, 5, 3, conv2_W, conv2_b, h1_f, 0, 1.0f, 1);

    // ---- head: h1 -> logits ----
    float* out_u = out + 0;
    float* out_n = out + (size_t)N_USER * 2;                      // 400000
    float* out_s = out + (size_t)(N_USER + N_NEWS) * 2;           // 600000
    float* out_f = out + (size_t)(N_USER + N_NEWS + N_SOURCE) * 2;// 610000
    head_kernel<<<(N_USER * 32 + 255) / 256, 256>>>(h1_u, Wl_user, bl_user, out_u, N_USER);
    head_kernel<<<(N_NEWS * 32 + 255) / 256, 256>>>(h1_n, Wl_news, bl_news, out_n, N_NEWS);
    head_kernel<<<(N_SOURCE * 32 + 255) / 256, 256>>>(h1_s, Wl_source, bl_source, out_s, N_SOURCE);
    head_kernel<<<(N_FOLLOWER * 32 + 255) / 256, 256>>>(h1_f, Wl_follower, bl_follower, out_f, N_FOLLOWER);
}

// round 3
// speedup vs baseline: 1.0469x; 1.0469x over previous
#include <cuda_runtime.h>
#include <cuda_bf16.h>
#include <cstdint>
#include <cstddef>

#define N_USER 200000
#define N_NEWS 100000
#define N_SOURCE 5000
#define N_FOLLOWER 200000
#define HDIM 128
#define E_POSTS 500000
#define E_PUB 100000
#define E_FOL 1000000

#define TOT_NODES (N_USER + N_NEWS + N_SOURCE + N_FOLLOWER)

// feature-buffer offsets (in floats)
#define OFF_U ((size_t)0)
#define OFF_N ((size_t)N_USER * HDIM)
#define OFF_S ((size_t)(N_USER + N_NEWS) * HDIM)
#define OFF_F ((size_t)(N_USER + N_NEWS + N_SOURCE) * HDIM)

// degree-array segment offsets (floats)
#define DS_POSTS_U 0
#define DS_POSTS_N 200000
#define DS_PUB_S   300000
#define DS_PUB_N   305000
#define DS_FOL_F   405000
#define DS_FOL_U   605000
#define DEG_TOTAL  805000

// scratch (device globals: allocation-free rule)
__device__ float g_bufA[(size_t)TOT_NODES * HDIM];
__device__ float g_bufB[(size_t)TOT_NODES * HDIM];
__device__ float g_agg[(size_t)N_USER * HDIM];
__device__ float g_deg[DEG_TOTAL];

// ---------------------------------------------------------------------------
__global__ void zero_kernel(float* __restrict__ p, size_t n4) {
    size_t i = (size_t)blockIdx.x * blockDim.x + threadIdx.x;
    size_t stride = (size_t)gridDim.x * blockDim.x;
    float4 z = make_float4(0.f, 0.f, 0.f, 0.f);
    float4* p4 = reinterpret_cast<float4*>(p);
    for (; i < n4; i += stride) p4[i] = z;
}

__global__ void count_kernel(const int* __restrict__ idx, int n, float* __restrict__ cnt) {
    int i = blockIdx.x * blockDim.x + threadIdx.x;
    int stride = gridDim.x * blockDim.x;
    for (; i < n; i += stride) atomicAdd(&cnt[idx[i]], 1.0f);
}

__global__ void rsqrt_kernel(float* __restrict__ p, int n) {
    int i = blockIdx.x * blockDim.x + threadIdx.x;
    int stride = gridDim.x * blockDim.x;
    for (; i < n; i += stride) {
        float v = p[i];
        p[i] = rsqrtf(v < 1.0f ? 1.0f : v);
    }
}

// one warp per edge: gather h_src * rsqrt(deg_out), vector-RED into agg[dst]
__global__ void scatter_kernel(const float* __restrict__ h,
                               const int* __restrict__ src,
                               const int* __restrict__ dst,
                               const float* __restrict__ rs_out,
                               float* __restrict__ agg, int E) {
    int warp = (blockIdx.x * blockDim.x + threadIdx.x) >> 5;
    int lane = threadIdx.x & 31;
    int nwarps = (gridDim.x * blockDim.x) >> 5;
    for (int e = warp; e < E; e += nwarps) {
        int s = src[e];
        int d = dst[e];
        float sc = rs_out[s];
        float4 v = *reinterpret_cast<const float4*>(h + (size_t)s * HDIM + lane * 4);
        v.x *= sc; v.y *= sc; v.z *= sc; v.w *= sc;
        float* a = agg + (size_t)d * HDIM + lane * 4;
        asm volatile("red.global.add.v4.f32 [%0], {%1,%2,%3,%4};"
                     :: "l"(a), "f"(v.x), "f"(v.y), "f"(v.z), "f"(v.w) : "memory");
    }
}

// ---------------------------------------------------------------------------
// Tensor-core GEMM: C[M,128] = epi( (rowscale?A*rs:A)[M,K] @ W[K,128] )
// fp32 emulated via bf16x3 split: A=Ah+Al, W=Wh+Wl, C += Ah*Wh + Ah*Wl + Al*Wh
// ---------------------------------------------------------------------------
#define A_STRIDE 24    // bf16 per smem A row (16 data + 8 pad -> 48B, conflict-free ldmatrix)
#define W_STRIDE 136   // bf16 per smem W row (128 data + 8 pad -> 272B)

__device__ __forceinline__ void mma16816(float* c, const uint32_t* a, const uint32_t* b) {
    asm volatile(
        "mma.sync.aligned.m16n8k16.row.col.f32.bf16.bf16.f32 "
        "{%0,%1,%2,%3}, {%4,%5,%6,%7}, {%8,%9}, {%0,%1,%2,%3};\n"
        : "+f"(c[0]), "+f"(c[1]), "+f"(c[2]), "+f"(c[3])
        : "r"(a[0]), "r"(a[1]), "r"(a[2]), "r"(a[3]), "r"(b[0]), "r"(b[1]));
}
__device__ __forceinline__ void ldsm_x4(uint32_t* r, const void* p) {
    uint32_t addr = (uint32_t)__cvta_generic_to_shared(p);
    asm volatile("ldmatrix.sync.aligned.m8n8.x4.shared.b16 {%0,%1,%2,%3}, [%4];"
                 : "=r"(r[0]), "=r"(r[1]), "=r"(r[2]), "=r"(r[3]) : "r"(addr));
}
__device__ __forceinline__ void ldsm_x4_t(uint32_t* r, const void* p) {
    uint32_t addr = (uint32_t)__cvta_generic_to_shared(p);
    asm volatile("ldmatrix.sync.aligned.m8n8.x4.trans.shared.b16 {%0,%1,%2,%3}, [%4];"
                 : "=r"(r[0]), "=r"(r[1]), "=r"(r[2]), "=r"(r[3]) : "r"(addr));
}
__device__ __forceinline__ uint32_t pack_bf2(__nv_bfloat16 a, __nv_bfloat16 b) {
    return (uint32_t)__bfloat16_as_ushort(a) | ((uint32_t)__bfloat16_as_ushort(b) << 16);
}

__global__ __launch_bounds__(256, 1) void tgemm_kernel(
    const float* __restrict__ A, const float* __restrict__ rowscale,
    const float* __restrict__ W, const float* __restrict__ bias,
    float* __restrict__ C, int M, int K,
    int accumulate, float scale, int do_act) {
    __shared__ __align__(16) __nv_bfloat16 As[2][128 * A_STRIDE];
    __shared__ __align__(16) __nv_bfloat16 Ws[2][16 * W_STRIDE];

    int tid = threadIdx.x;
    int lane = tid & 31;
    int warp = tid >> 5;
    int wm = warp & 1;   // 0..1 -> 64-row band
    int wn = warp >> 1;  // 0..3 -> 32-col band
    int block_row = blockIdx.x * 128;

    float c[4][4][4];
#pragma unroll
    for (int mt = 0; mt < 4; mt++)
#pragma unroll
        for (int nt = 0; nt < 4; nt++)
#pragma unroll
            for (int j = 0; j < 4; j++) c[mt][nt][j] = 0.f;

    int nchunk = (K + 15) / 16;
    for (int ch = 0; ch < nchunk; ch++) {
        int k0 = ch * 16;
        // ---- load + split A chunk: 128 rows x 16 k ----
        {
            int row = tid >> 1;
            int koff = (tid & 1) * 8;
            float v[8];
            int grow = block_row + row;
            if (grow < M) {
                const float* ap = A + (size_t)grow * K + k0 + koff;
                if (k0 + koff + 7 < K) {
                    float4 v0 = *reinterpret_cast<const float4*>(ap);
                    float4 v1 = *reinterpret_cast<const float4*>(ap + 4);
                    v[0] = v0.x; v[1] = v0.y; v[2] = v0.z; v[3] = v0.w;
                    v[4] = v1.x; v[5] = v1.y; v[6] = v1.z; v[7] = v1.w;
                } else {
#pragma unroll
                    for (int j = 0; j < 8; j++)
                        v[j] = (k0 + koff + j < K) ? ap[j] : 0.f;
                }
                if (rowscale) {
                    float s = rowscale[grow];
#pragma unroll
                    for (int j = 0; j < 8; j++) v[j] *= s;
                }
            } else {
#pragma unroll
                for (int j = 0; j < 8; j++) v[j] = 0.f;
            }
            uint32_t hp[4], lp[4];
#pragma unroll
            for (int j = 0; j < 4; j++) {
                __nv_bfloat16 h0 = __float2bfloat16_rn(v[2 * j]);
                __nv_bfloat16 h1 = __float2bfloat16_rn(v[2 * j + 1]);
                __nv_bfloat16 l0 = __float2bfloat16_rn(v[2 * j] - __bfloat162float(h0));
                __nv_bfloat16 l1 = __float2bfloat16_rn(v[2 * j + 1] - __bfloat162float(h1));
                hp[j] = pack_bf2(h0, h1);
                lp[j] = pack_bf2(l0, l1);
            }
            uint32_t off = row * A_STRIDE + koff;
            *reinterpret_cast<uint4*>(&As[0][off]) = make_uint4(hp[0], hp[1], hp[2], hp[3]);
            *reinterpret_cast<uint4*>(&As[1][off]) = make_uint4(lp[0], lp[1], lp[2], lp[3]);
        }
        // ---- load + split W chunk: 16 rows x 128 n ----
        {
            int row = tid >> 4;        // 0..15
            int col = (tid & 15) * 8;  // 0..120
            float v[8];
            if (k0 + row < K) {
                const float* wp = W + (size_t)(k0 + row) * HDIM + col;
                float4 v0 = *reinterpret_cast<const float4*>(wp);
                float4 v1 = *reinterpret_cast<const float4*>(wp + 4);
                v[0] = v0.x; v[1] = v0.y; v[2] = v0.z; v[3] = v0.w;
                v[4] = v1.x; v[5] = v1.y; v[6] = v1.z; v[7] = v1.w;
            } else {
#pragma unroll
                for (int j = 0; j < 8; j++) v[j] = 0.f;
            }
            uint32_t hp[4], lp[4];
#pragma unroll
            for (int j = 0; j < 4; j++) {
                __nv_bfloat16 h0 = __float2bfloat16_rn(v[2 * j]);
                __nv_bfloat16 h1 = __float2bfloat16_rn(v[2 * j + 1]);
                __nv_bfloat16 l0 = __float2bfloat16_rn(v[2 * j] - __bfloat162float(h0));
                __nv_bfloat16 l1 = __float2bfloat16_rn(v[2 * j + 1] - __bfloat162float(h1));
                hp[j] = pack_bf2(h0, h1);
                lp[j] = pack_bf2(l0, l1);
            }
            uint32_t off = row * W_STRIDE + col;
            *reinterpret_cast<uint4*>(&Ws[0][off]) = make_uint4(hp[0], hp[1], hp[2], hp[3]);
            *reinterpret_cast<uint4*>(&Ws[1][off]) = make_uint4(lp[0], lp[1], lp[2], lp[3]);
        }
        __syncthreads();

        // ---- B fragments (per-warp 32 cols = 4 n8 tiles) ----
        uint32_t bh[4][2], bl[4][2];
#pragma unroll
        for (int half = 0; half < 2; half++) {
            uint32_t off = (lane & 15) * W_STRIDE + wn * 32 + half * 16 + (lane >> 4) * 8;
            uint32_t r[4];
            ldsm_x4_t(r, &Ws[0][off]);
            bh[half * 2][0] = r[0]; bh[half * 2][1] = r[1];
            bh[half * 2 + 1][0] = r[2]; bh[half * 2 + 1][1] = r[3];
            ldsm_x4_t(r, &Ws[1][off]);
            bl[half * 2][0] = r[0]; bl[half * 2][1] = r[1];
            bl[half * 2 + 1][0] = r[2]; bl[half * 2 + 1][1] = r[3];
        }
        // ---- A fragments + MMAs ----
#pragma unroll
        for (int mt = 0; mt < 4; mt++) {
            uint32_t off = (wm * 64 + mt * 16 + (lane & 15)) * A_STRIDE + (lane >> 4) * 8;
            uint32_t ah[4], al[4];
            ldsm_x4(ah, &As[0][off]);
            ldsm_x4(al, &As[1][off]);
#pragma unroll
            for (int nt = 0; nt < 4; nt++) {
                mma16816(c[mt][nt], ah, bh[nt]);
                mma16816(c[mt][nt], ah, bl[nt]);
                mma16816(c[mt][nt], al, bh[nt]);
            }
        }
        __syncthreads();
    }

    // ---- epilogue ----
#pragma unroll
    for (int mt = 0; mt < 4; mt++) {
#pragma unroll
        for (int nt = 0; nt < 4; nt++) {
            int col = wn * 32 + nt * 8 + (lane & 3) * 2;
            float b0 = bias ? bias[col] : 0.f;
            float b1 = bias ? bias[col + 1] : 0.f;
#pragma unroll
            for (int h = 0; h < 2; h++) {
                int row = block_row + wm * 64 + mt * 16 + (lane >> 2) + h * 8;
                if (row >= M) continue;
                float r0 = c[mt][nt][2 * h] + b0;
                float r1 = c[mt][nt][2 * h + 1] + b1;
                float* cp = C + (size_t)row * HDIM + col;
                if (accumulate) {
                    float2 o = *reinterpret_cast<float2*>(cp);
                    r0 += o.x; r1 += o.y;
                }
                r0 *= scale; r1 *= scale;
                if (do_act) {
                    r0 = r0 > 0.f ? r0 : 0.01f * r0;
                    r1 = r1 > 0.f ? r1 : 0.01f * r1;
                }
                *reinterpret_cast<float2*>(cp) = make_float2(r0, r1);
            }
        }
    }
}

// final head: out[r,0:2] = h1[r,:] @ Wl[128,2] + bl   (one warp per row)
__global__ void head_kernel(const float* __restrict__ h1, const float* __restrict__ Wl,
                            const float* __restrict__ bl, float* __restrict__ out, int Nrows) {
    int warp = (blockIdx.x * blockDim.x + threadIdx.x) >> 5;
    int lane = threadIdx.x & 31;
    int nwarps = (gridDim.x * blockDim.x) >> 5;
    int k = lane * 4;
    float w00 = Wl[(k + 0) * 2], w01 = Wl[(k + 0) * 2 + 1];
    float w10 = Wl[(k + 1) * 2], w11 = Wl[(k + 1) * 2 + 1];
    float w20 = Wl[(k + 2) * 2], w21 = Wl[(k + 2) * 2 + 1];
    float w30 = Wl[(k + 3) * 2], w31 = Wl[(k + 3) * 2 + 1];
    for (int r = warp; r < Nrows; r += nwarps) {
        float4 v = *reinterpret_cast<const float4*>(h1 + (size_t)r * HDIM + k);
        float p0 = v.x * w00 + v.y * w10 + v.z * w20 + v.w * w30;
        float p1 = v.x * w01 + v.y * w11 + v.z * w21 + v.w * w31;
#pragma unroll
        for (int off = 16; off; off >>= 1) {
            p0 += __shfl_xor_sync(0xffffffffu, p0, off);
            p1 += __shfl_xor_sync(0xffffffffu, p1, off);
        }
        if (lane == 0) {
            out[(size_t)r * 2 + 0] = p0 + bl[0];
            out[(size_t)r * 2 + 1] = p1 + bl[1];
        }
    }
}

// ---------------------------------------------------------------------------
extern "C" void kernel_launch(void* const* d_in, const int* in_sizes, int n_in,
                              void* d_out, int out_size) {
    const float* x_user = (const float*)d_in[0];
    const float* x_news = (const float*)d_in[1];
    const float* x_source = (const float*)d_in[2];
    const float* x_follower = (const float*)d_in[3];
    const float* Wi1_user = (const float*)d_in[4];
    const float* bi1_user = (const float*)d_in[5];
    const float* Wi1_news = (const float*)d_in[6];
    const float* bi1_news = (const float*)d_in[7];
    const float* Wi1_source = (const float*)d_in[8];
    const float* bi1_source = (const float*)d_in[9];
    const float* Wi1_follower = (const float*)d_in[10];
    const float* bi1_follower = (const float*)d_in[11];
    const float* Wi2 = (const float*)d_in[12];
    const float* bi2 = (const float*)d_in[13];
    const float* conv1_W = (const float*)d_in[14];
    const float* conv1_b = (const float*)d_in[15];
    const float* conv2_W = (const float*)d_in[16];
    const float* conv2_b = (const float*)d_in[17];
    const float* Wl_user = (const float*)d_in[18];
    const float* bl_user = (const float*)d_in[19];
    const float* Wl_news = (const float*)d_in[20];
    const float* bl_news = (const float*)d_in[21];
    const float* Wl_source = (const float*)d_in[22];
    const float* bl_source = (const float*)d_in[23];
    const float* Wl_follower = (const float*)d_in[24];
    const float* bl_follower = (const float*)d_in[25];
    const int* posts_u = (const int*)d_in[26];
    const int* posts_n = (const int*)d_in[27];
    const int* pub_s = (const int*)d_in[28];
    const int* pub_n = (const int*)d_in[29];
    const int* fol_f = (const int*)d_in[30];
    const int* fol_u = (const int*)d_in[31];
    float* out = (float*)d_out;

    float *bufA, *bufB, *agg, *deg;
    cudaGetSymbolAddress((void**)&bufA, g_bufA);
    cudaGetSymbolAddress((void**)&bufB, g_bufB);
    cudaGetSymbolAddress((void**)&agg, g_agg);
    cudaGetSymbolAddress((void**)&deg, g_deg);

    auto zero = [](float* p, size_t n) {
        int blocks = (int)((n / 4 + 255) / 256);
        if (blocks > 4096) blocks = 4096;
        zero_kernel<<<blocks, 256>>>(p, n / 4);
    };
    auto gemm = [](const float* A, const float* rs, const float* W, const float* b,
                   float* C, int M, int K, int acc, float scale, int act) {
        tgemm_kernel<<<(M + 127) / 128, 256>>>(A, rs, W, b, C, M, K, acc, scale, act);
    };
    auto scatter = [](const float* h, const int* s, const int* d, const float* rs,
                      float* aggp, int E) {
        int blocks = (E + 7) / 8;
        scatter_kernel<<<blocks, 256>>>(h, s, d, rs, aggp, E);
    };

    // ---- degrees ----
    zero(deg, (size_t)DEG_TOTAL);
    count_kernel<<<2048, 256>>>(posts_u, E_POSTS, deg + DS_POSTS_U);
    count_kernel<<<2048, 256>>>(posts_n, E_POSTS, deg + DS_POSTS_N);
    count_kernel<<<512, 256>>>(pub_s, E_PUB, deg + DS_PUB_S);
    count_kernel<<<512, 256>>>(pub_n, E_PUB, deg + DS_PUB_N);
    count_kernel<<<4096, 256>>>(fol_f, E_FOL, deg + DS_FOL_F);
    count_kernel<<<4096, 256>>>(fol_u, E_FOL, deg + DS_FOL_U);
    rsqrt_kernel<<<2048, 256>>>(deg, DEG_TOTAL);

    // ---- dense layer 1: x -> bufA ----
    gemm(x_user, nullptr, Wi1_user, bi1_user, bufA + OFF_U, N_USER, 128, 0, 1.f, 1);
    gemm(x_news, nullptr, Wi1_news, bi1_news, bufA + OFF_N, N_NEWS, 300, 0, 1.f, 1);
    gemm(x_source, nullptr, Wi1_source, bi1_source, bufA + OFF_S, N_SOURCE, 128, 0, 1.f, 1);
    gemm(x_follower, nullptr, Wi1_follower, bi1_follower, bufA + OFF_F, N_FOLLOWER, 128, 0, 1.f, 1);

    // ---- dense layer 2: bufA -> bufB ----
    const size_t HH = (size_t)HDIM * HDIM;
    gemm(bufA + OFF_U, nullptr, Wi2 + 0 * HH, bi2 + 0 * HDIM, bufB + OFF_U, N_USER, 128, 0, 1.f, 1);
    gemm(bufA + OFF_N, nullptr, Wi2 + 1 * HH, bi2 + 1 * HDIM, bufB + OFF_N, N_NEWS, 128, 0, 1.f, 1);
    gemm(bufA + OFF_S, nullptr, Wi2 + 2 * HH, bi2 + 2 * HDIM, bufB + OFF_S, N_SOURCE, 128, 0, 1.f, 1);
    gemm(bufA + OFF_F, nullptr, Wi2 + 3 * HH, bi2 + 3 * HDIM, bufB + OFF_F, N_FOLLOWER, 128, 0, 1.f, 1);

    // relation table
    struct Rel { const int* src; const int* dst; int E; size_t hoff; int rs_out; int rs_in; int n_dst; };
    Rel rel[6] = {
        {posts_u, posts_n, E_POSTS, OFF_U, DS_POSTS_U, DS_POSTS_N, N_NEWS},
        {posts_n, posts_u, E_POSTS, OFF_N, DS_POSTS_N, DS_POSTS_U, N_USER},
        {pub_s, pub_n, E_PUB, OFF_S, DS_PUB_S, DS_PUB_N, N_NEWS},
        {pub_n, pub_s, E_PUB, OFF_N, DS_PUB_N, DS_PUB_S, N_SOURCE},
        {fol_f, fol_u, E_FOL, OFF_F, DS_FOL_F, DS_FOL_U, N_USER},
        {fol_u, fol_f, E_FOL, OFF_U, DS_FOL_U, DS_FOL_F, N_FOLLOWER},
    };

    auto run_rel = [&](const float* hbase, int r, int i, const float* Wc, const float* bc,
                       float* outp, int acc, float scale, int act) {
        const Rel& R = rel[r];
        zero(agg, (size_t)R.n_dst * HDIM);
        scatter(hbase + R.hoff, R.src, R.dst, deg + R.rs_out, agg, R.E);
        gemm(agg, deg + R.rs_in, Wc + ((size_t)i * 6 + r) * HH, bc + ((size_t)i * 6 + r) * HDIM,
             outp, R.n_dst, HDIM, acc, scale, act);
    };

    // ---- conv1: bufB -> bufA ----
    run_rel(bufB, 1, 0, conv1_W, conv1_b, bufA + OFF_U, 0, 1.0f, 0);
    run_rel(bufB, 4, 0, conv1_W, conv1_b, bufA + OFF_U, 1, 0.5f, 1);
    run_rel(bufB, 0, 1, conv1_W, conv1_b, bufA + OFF_N, 0, 1.0f, 0);
    run_rel(bufB, 2, 1, conv1_W, conv1_b, bufA + OFF_N, 1, 0.5f, 1);
    run_rel(bufB, 3, 2, conv1_W, conv1_b, bufA + OFF_S, 0, 1.0f, 1);
    run_rel(bufB, 5, 3, conv1_W, conv1_b, bufA + OFF_F, 0, 1.0f, 1);

    // ---- conv2: bufA -> h1 region of d_out ----
    const size_t H1_BASE = (size_t)TOT_NODES * 2;
    float* h1_u = out + H1_BASE + OFF_U;
    float* h1_n = out + H1_BASE + OFF_N;
    float* h1_s = out + H1_BASE + OFF_S;
    float* h1_f = out + H1_BASE + OFF_F;
    run_rel(bufA, 1, 0, conv2_W, conv2_b, h1_u, 0, 1.0f, 0);
    run_rel(bufA, 4, 0, conv2_W, conv2_b, h1_u, 1, 0.5f, 1);
    run_rel(bufA, 0, 1, conv2_W, conv2_b, h1_n, 0, 1.0f, 0);
    run_rel(bufA, 2, 1, conv2_W, conv2_b, h1_n, 1, 0.5f, 1);
    run_rel(bufA, 3, 2, conv2_W, conv2_b, h1_s, 0, 1.0f, 1);
    run_rel(bufA, 5, 3, conv2_W, conv2_b, h1_f, 0, 1.0f, 1);

    // ---- head: h1 -> logits ----
    float* out_u = out + 0;
    float* out_n = out + (size_t)N_USER * 2;
    float* out_s = out + (size_t)(N_USER + N_NEWS) * 2;
    float* out_f = out + (size_t)(N_USER + N_NEWS + N_SOURCE) * 2;
    head_kernel<<<(N_USER * 32 + 255) / 256, 256>>>(h1_u, Wl_user, bl_user, out_u, N_USER);
    head_kernel<<<(N_NEWS * 32 + 255) / 256, 256>>>(h1_n, Wl_news, bl_news, out_n, N_NEWS);
    head_kernel<<<(N_SOURCE * 32 + 255) / 256, 256>>>(h1_s, Wl_source, bl_source, out_s, N_SOURCE);
    head_kernel<<<(N_FOLLOWER * 32 + 255) / 256, 256>>>(h1_f, Wl_follower, bl_follower, out_f, N_FOLLOWER);
}

// round 9
// speedup vs baseline: 1.3004x; 1.2421x over previous
#include <cuda_runtime.h>
#include <cuda_bf16.h>
#include <cstdint>
#include <cstddef>

#define N_USER 200000
#define N_NEWS 100000
#define N_SOURCE 5000
#define N_FOLLOWER 200000
#define HDIM 128
#define E_POSTS 500000
#define E_PUB 100000
#define E_FOL 1000000

#define TOT_NODES (N_USER + N_NEWS + N_SOURCE + N_FOLLOWER)

#define OFF_U ((size_t)0)
#define OFF_N ((size_t)N_USER * HDIM)
#define OFF_S ((size_t)(N_USER + N_NEWS) * HDIM)
#define OFF_F ((size_t)(N_USER + N_NEWS + N_SOURCE) * HDIM)

// degree/count segment offsets (one per index array)
#define DS_POSTS_U 0
#define DS_POSTS_N 200000
#define DS_PUB_S   300000
#define DS_PUB_N   305000
#define DS_FOL_F   405000
#define DS_FOL_U   605000
#define DEG_TOTAL  805000

// row_ptr segment offsets (per relation, length n_dst+1)
#define RP0 0         // news   100001
#define RP1 100001    // user   200001
#define RP2 300002    // news   100001
#define RP3 400003    // source 5001
#define RP4 405004    // user   200001
#define RP5 605005    // follower 200001
#define RP_TOTAL 805006

// edge-list segment offsets
#define EL0 0
#define EL1 500000
#define EL2 1000000
#define EL3 1100000
#define EL4 1200000
#define EL5 2200000
#define EL_TOTAL 3200000

__device__ float g_bufA[(size_t)TOT_NODES * HDIM];
__device__ float g_bufB[(size_t)TOT_NODES * HDIM];
__device__ float g_agg[(size_t)N_USER * 256];
__device__ float g_deg[DEG_TOTAL];
__device__ int   g_cnt[DEG_TOTAL];
__device__ int   g_cur[DEG_TOTAL];
__device__ int   g_rp[RP_TOTAL];
__device__ int   g_el[EL_TOTAL];

// ---------------------------------------------------------------------------
__global__ void zero4_kernel(float4* __restrict__ p, size_t n4) {
    size_t i = (size_t)blockIdx.x * blockDim.x + threadIdx.x;
    size_t stride = (size_t)gridDim.x * blockDim.x;
    float4 z = make_float4(0.f, 0.f, 0.f, 0.f);
    for (; i < n4; i += stride) p[i] = z;
}

__global__ void counti_kernel(const int* __restrict__ idx, int n, int* __restrict__ cnt) {
    int i = blockIdx.x * blockDim.x + threadIdx.x;
    int stride = gridDim.x * blockDim.x;
    for (; i < n; i += stride) atomicAdd(&cnt[idx[i]], 1);
}

__global__ void rsqrt_cnt_kernel(const int* __restrict__ cnt, float* __restrict__ deg, int n) {
    int i = blockIdx.x * blockDim.x + threadIdx.x;
    int stride = gridDim.x * blockDim.x;
    for (; i < n; i += stride) {
        int c = cnt[i];
        deg[i] = rsqrtf((float)(c < 1 ? 1 : c));
    }
}

// 6-relation parallel exclusive scan: block b scans relation b's dst counts
__global__ __launch_bounds__(1024) void scan6_kernel(const int* __restrict__ cnt,
                                                     int* __restrict__ rp) {
    const int segs[6] = {DS_POSTS_N, DS_POSTS_U, DS_PUB_N, DS_PUB_S, DS_FOL_U, DS_FOL_F};
    const int ns[6]   = {N_NEWS, N_USER, N_NEWS, N_SOURCE, N_USER, N_FOLLOWER};
    const int rpo[6]  = {RP0, RP1, RP2, RP3, RP4, RP5};
    int r = blockIdx.x;
    const int* c = cnt + segs[r];
    int* out = rp + rpo[r];
    int n = ns[r];
    int tid = threadIdx.x;
    int lane = tid & 31;
    int wid = tid >> 5;
    __shared__ int wsum[32];
    __shared__ int carry;
    if (tid == 0) { carry = 0; out[0] = 0; }
    __syncthreads();
    for (int base = 0; base < n; base += 1024) {
        int v = (base + tid < n) ? c[base + tid] : 0;
        int x = v;
#pragma unroll
        for (int o = 1; o < 32; o <<= 1) {
            int y = __shfl_up_sync(0xffffffffu, x, o);
            if (lane >= o) x += y;
        }
        if (lane == 31) wsum[wid] = x;
        __syncthreads();
        if (wid == 0) {
            int s = wsum[lane];
#pragma unroll
            for (int o = 1; o < 32; o <<= 1) {
                int y = __shfl_up_sync(0xffffffffu, s, o);
                if (lane >= o) s += y;
            }
            wsum[lane] = s;
        }
        __syncthreads();
        int pre = (wid > 0) ? wsum[wid - 1] : 0;
        int incl = carry + pre + x;
        if (base + tid < n) out[base + tid + 1] = incl;
        __syncthreads();
        if (tid == 1023) carry = incl;
        __syncthreads();
    }
}

__global__ void fill_kernel(const int* __restrict__ src, const int* __restrict__ dst, int E,
                            const int* __restrict__ rp, int* __restrict__ cur,
                            int* __restrict__ el) {
    int i = blockIdx.x * blockDim.x + threadIdx.x;
    int stride = gridDim.x * blockDim.x;
    for (; i < E; i += stride) {
        int d = dst[i];
        int p = atomicAdd(&cur[d], 1);
        el[rp[d] + p] = src[i];
    }
}

// CSR gather: one warp per dst row; agg[row, colofs:colofs+128] = rs_in[row] *
//   sum_e rs_out[src_e] * h[src_e, :]
__global__ void gather_kernel(const float* __restrict__ h, const int* __restrict__ rp,
                              const int* __restrict__ el, const float* __restrict__ rs_src,
                              const float* __restrict__ rs_dst, float* __restrict__ agg,
                              int colofs, int n_dst) {
    int warp = (blockIdx.x * blockDim.x + threadIdx.x) >> 5;
    int lane = threadIdx.x & 31;
    int nwarps = (gridDim.x * blockDim.x) >> 5;
    for (int row = warp; row < n_dst; row += nwarps) {
        int beg = rp[row], end = rp[row + 1];
        float4 acc = make_float4(0.f, 0.f, 0.f, 0.f);
        for (int e = beg; e < end; e++) {
            int s = el[e];
            float sc = rs_src[s];
            float4 v = *reinterpret_cast<const float4*>(h + (size_t)s * HDIM + lane * 4);
            acc.x += sc * v.x; acc.y += sc * v.y; acc.z += sc * v.z; acc.w += sc * v.w;
        }
        float ri = rs_dst[row];
        acc.x *= ri; acc.y *= ri; acc.z *= ri; acc.w *= ri;
        *reinterpret_cast<float4*>(agg + (size_t)row * 256 + colofs + lane * 4) = acc;
    }
}

// ---------------------------------------------------------------------------
// bf16x3 HMMA GEMM, K-chunk 128 with full-chunk smem residency.
// C[M,128] = epi( A[M,K](lda) @ [W0;W1][K,128] + b0 + b1 ), epi: *scale, lrelu?
// ---------------------------------------------------------------------------
#define TSTR 136   // bf16 row stride in smem (128 data + 8 pad -> 272B, 16B-divisible)
#define SM_BYTES (4 * 128 * TSTR * 2)   // AH, AL, BH, BL -> 139264 B

__device__ __forceinline__ void mma16816(float* c, const uint32_t* a, const uint32_t* b) {
    asm volatile(
        "mma.sync.aligned.m16n8k16.row.col.f32.bf16.bf16.f32 "
        "{%0,%1,%2,%3}, {%4,%5,%6,%7}, {%8,%9}, {%0,%1,%2,%3};\n"
        : "+f"(c[0]), "+f"(c[1]), "+f"(c[2]), "+f"(c[3])
        : "r"(a[0]), "r"(a[1]), "r"(a[2]), "r"(a[3]), "r"(b[0]), "r"(b[1]));
}
__device__ __forceinline__ void ldsm_x4(uint32_t* r, const void* p) {
    uint32_t addr = (uint32_t)__cvta_generic_to_shared(p);
    asm volatile("ldmatrix.sync.aligned.m8n8.x4.shared.b16 {%0,%1,%2,%3}, [%4];"
                 : "=r"(r[0]), "=r"(r[1]), "=r"(r[2]), "=r"(r[3]) : "r"(addr));
}
__device__ __forceinline__ void ldsm_x4_t(uint32_t* r, const void* p) {
    uint32_t addr = (uint32_t)__cvta_generic_to_shared(p);
    asm volatile("ldmatrix.sync.aligned.m8n8.x4.trans.shared.b16 {%0,%1,%2,%3}, [%4];"
                 : "=r"(r[0]), "=r"(r[1]), "=r"(r[2]), "=r"(r[3]) : "r"(addr));
}
__device__ __forceinline__ uint32_t pack_hi2(float a, float b, uint32_t* lo) {
    __nv_bfloat16 h0 = __float2bfloat16_rn(a);
    __nv_bfloat16 h1 = __float2bfloat16_rn(b);
    __nv_bfloat16 l0 = __float2bfloat16_rn(a - __bfloat162float(h0));
    __nv_bfloat16 l1 = __float2bfloat16_rn(b - __bfloat162float(h1));
    *lo = (uint32_t)__bfloat16_as_ushort(l0) | ((uint32_t)__bfloat16_as_ushort(l1) << 16);
    return (uint32_t)__bfloat16_as_ushort(h0) | ((uint32_t)__bfloat16_as_ushort(h1) << 16);
}

__global__ __launch_bounds__(256, 1) void tgemm_kernel(
    const float* __restrict__ A, int lda,
    const float* __restrict__ W0, const float* __restrict__ W1, int K0, int K,
    const float* __restrict__ b0, const float* __restrict__ b1,
    float* __restrict__ C, int M, float scale, int do_act) {
    extern __shared__ __align__(16) char smraw[];
    __nv_bfloat16* AH = reinterpret_cast<__nv_bfloat16*>(smraw);
    __nv_bfloat16* AL = AH + 128 * TSTR;
    __nv_bfloat16* BH = AL + 128 * TSTR;
    __nv_bfloat16* BL = BH + 128 * TSTR;

    int tid = threadIdx.x;
    int lane = tid & 31;
    int warp = tid >> 5;
    int wm = warp & 1;
    int wn = warp >> 1;
    int block_row = blockIdx.x * 128;

    float c[4][4][4];
#pragma unroll
    for (int mt = 0; mt < 4; mt++)
#pragma unroll
        for (int nt = 0; nt < 4; nt++)
#pragma unroll
            for (int j = 0; j < 4; j++) c[mt][nt][j] = 0.f;

    for (int kbase = 0; kbase < K; kbase += 128) {
        int kcount = K - kbase; if (kcount > 128) kcount = 128;
        // ---- stage A chunk: 128 rows x 128 k ----
        for (int idx = tid; idx < 128 * 16; idx += 256) {
            int row = idx >> 4;
            int kl = (idx & 15) * 8;
            float v[8];
#pragma unroll
            for (int j = 0; j < 8; j++) v[j] = 0.f;
            int grow = block_row + row;
            int gk = kbase + kl;
            if (grow < M && gk < K) {
                const float* ap = A + (size_t)grow * lda + gk;
                if (gk + 7 < K) {
                    float4 v0 = *reinterpret_cast<const float4*>(ap);
                    float4 v1 = *reinterpret_cast<const float4*>(ap + 4);
                    v[0] = v0.x; v[1] = v0.y; v[2] = v0.z; v[3] = v0.w;
                    v[4] = v1.x; v[5] = v1.y; v[6] = v1.z; v[7] = v1.w;
                } else {
#pragma unroll
                    for (int j = 0; j < 8; j++)
                        if (gk + j < K) v[j] = ap[j];
                }
            }
            uint32_t hp[4], lp[4];
#pragma unroll
            for (int j = 0; j < 4; j++) hp[j] = pack_hi2(v[2 * j], v[2 * j + 1], &lp[j]);
            uint32_t off = (uint32_t)(row * TSTR + kl);
            *reinterpret_cast<uint4*>(&AH[off]) = make_uint4(hp[0], hp[1], hp[2], hp[3]);
            *reinterpret_cast<uint4*>(&AL[off]) = make_uint4(lp[0], lp[1], lp[2], lp[3]);
        }
        // ---- stage W chunk: 128 k-rows x 128 n ----
        for (int idx = tid; idx < 128 * 16; idx += 256) {
            int kr = idx >> 4;
            int nl = (idx & 15) * 8;
            float v[8];
#pragma unroll
            for (int j = 0; j < 8; j++) v[j] = 0.f;
            int gk = kbase + kr;
            if (gk < K) {
                const float* wp = (gk < K0) ? W0 + (size_t)gk * HDIM + nl
                                            : W1 + (size_t)(gk - K0) * HDIM + nl;
                float4 v0 = *reinterpret_cast<const float4*>(wp);
                float4 v1 = *reinterpret_cast<const float4*>(wp + 4);
                v[0] = v0.x; v[1] = v0.y; v[2] = v0.z; v[3] = v0.w;
                v[4] = v1.x; v[5] = v1.y; v[6] = v1.z; v[7] = v1.w;
            }
            uint32_t hp[4], lp[4];
#pragma unroll
            for (int j = 0; j < 4; j++) hp[j] = pack_hi2(v[2 * j], v[2 * j + 1], &lp[j]);
            uint32_t off = (uint32_t)(kr * TSTR + nl);
            *reinterpret_cast<uint4*>(&BH[off]) = make_uint4(hp[0], hp[1], hp[2], hp[3]);
            *reinterpret_cast<uint4*>(&BL[off]) = make_uint4(lp[0], lp[1], lp[2], lp[3]);
        }
        __syncthreads();

        int nsteps = (kcount + 15) / 16;
        for (int s = 0; s < nsteps; s++) {
            // B fragments for this k-step: 4 n8-tiles (hi & lo)
            uint32_t bh[4][2], bl[4][2];
#pragma unroll
            for (int half = 0; half < 2; half++) {
                uint32_t off = (uint32_t)((s * 16 + (lane & 15)) * TSTR + wn * 32 +
                                          half * 16 + (lane >> 4) * 8);
                uint32_t r[4];
                ldsm_x4_t(r, &BH[off]);
                bh[half * 2][0] = r[0]; bh[half * 2][1] = r[1];
                bh[half * 2 + 1][0] = r[2]; bh[half * 2 + 1][1] = r[3];
                ldsm_x4_t(r, &BL[off]);
                bl[half * 2][0] = r[0]; bl[half * 2][1] = r[1];
                bl[half * 2 + 1][0] = r[2]; bl[half * 2 + 1][1] = r[3];
            }
#pragma unroll
            for (int mt = 0; mt < 4; mt++) {
                uint32_t off = (uint32_t)((wm * 64 + mt * 16 + (lane & 15)) * TSTR +
                                          s * 16 + (lane >> 4) * 8);
                uint32_t ah[4], al[4];
                ldsm_x4(ah, &AH[off]);
                ldsm_x4(al, &AL[off]);
#pragma unroll
                for (int nt = 0; nt < 4; nt++) {
                    mma16816(c[mt][nt], ah, bh[nt]);
                    mma16816(c[mt][nt], ah, bl[nt]);
                    mma16816(c[mt][nt], al, bh[nt]);
                }
            }
        }
        __syncthreads();
    }

    // ---- epilogue ----
#pragma unroll
    for (int mt = 0; mt < 4; mt++) {
#pragma unroll
        for (int nt = 0; nt < 4; nt++) {
            int col = wn * 32 + nt * 8 + (lane & 3) * 2;
            float bb0 = (b0 ? b0[col] : 0.f) + (b1 ? b1[col] : 0.f);
            float bb1 = (b0 ? b0[col + 1] : 0.f) + (b1 ? b1[col + 1] : 0.f);
#pragma unroll
            for (int h = 0; h < 2; h++) {
                int row = block_row + wm * 64 + mt * 16 + (lane >> 2) + h * 8;
                if (row >= M) continue;
                float r0 = (c[mt][nt][2 * h] + bb0) * scale;
                float r1 = (c[mt][nt][2 * h + 1] + bb1) * scale;
                if (do_act) {
                    r0 = r0 > 0.f ? r0 : 0.01f * r0;
                    r1 = r1 > 0.f ? r1 : 0.01f * r1;
                }
                *reinterpret_cast<float2*>(C + (size_t)row * HDIM + col) = make_float2(r0, r1);
            }
        }
    }
}

// final head: out[r,0:2] = h1[r,:] @ Wl[128,2] + bl
__global__ void head_kernel(const float* __restrict__ h1, const float* __restrict__ Wl,
                            const float* __restrict__ bl, float* __restrict__ out, int Nrows) {
    int warp = (blockIdx.x * blockDim.x + threadIdx.x) >> 5;
    int lane = threadIdx.x & 31;
    int nwarps = (gridDim.x * blockDim.x) >> 5;
    int k = lane * 4;
    float w00 = Wl[(k + 0) * 2], w01 = Wl[(k + 0) * 2 + 1];
    float w10 = Wl[(k + 1) * 2], w11 = Wl[(k + 1) * 2 + 1];
    float w20 = Wl[(k + 2) * 2], w21 = Wl[(k + 2) * 2 + 1];
    float w30 = Wl[(k + 3) * 2], w31 = Wl[(k + 3) * 2 + 1];
    for (int r = warp; r < Nrows; r += nwarps) {
        float4 v = *reinterpret_cast<const float4*>(h1 + (size_t)r * HDIM + k);
        float p0 = v.x * w00 + v.y * w10 + v.z * w20 + v.w * w30;
        float p1 = v.x * w01 + v.y * w11 + v.z * w21 + v.w * w31;
#pragma unroll
        for (int off = 16; off; off >>= 1) {
            p0 += __shfl_xor_sync(0xffffffffu, p0, off);
            p1 += __shfl_xor_sync(0xffffffffu, p1, off);
        }
        if (lane == 0) {
            out[(size_t)r * 2 + 0] = p0 + bl[0];
            out[(size_t)r * 2 + 1] = p1 + bl[1];
        }
    }
}

// ---------------------------------------------------------------------------
extern "C" void kernel_launch(void* const* d_in, const int* in_sizes, int n_in,
                              void* d_out, int out_size) {
    const float* x_user = (const float*)d_in[0];
    const float* x_news = (const float*)d_in[1];
    const float* x_source = (const float*)d_in[2];
    const float* x_follower = (const float*)d_in[3];
    const float* Wi1_user = (const float*)d_in[4];
    const float* bi1_user = (const float*)d_in[5];
    const float* Wi1_news = (const float*)d_in[6];
    const float* bi1_news = (const float*)d_in[7];
    const float* Wi1_source = (const float*)d_in[8];
    const float* bi1_source = (const float*)d_in[9];
    const float* Wi1_follower = (const float*)d_in[10];
    const float* bi1_follower = (const float*)d_in[11];
    const float* Wi2 = (const float*)d_in[12];
    const float* bi2 = (const float*)d_in[13];
    const float* conv1_W = (const float*)d_in[14];
    const float* conv1_b = (const float*)d_in[15];
    const float* conv2_W = (const float*)d_in[16];
    const float* conv2_b = (const float*)d_in[17];
    const float* Wl_user = (const float*)d_in[18];
    const float* bl_user = (const float*)d_in[19];
    const float* Wl_news = (const float*)d_in[20];
    const float* bl_news = (const float*)d_in[21];
    const float* Wl_source = (const float*)d_in[22];
    const float* bl_source = (const float*)d_in[23];
    const float* Wl_follower = (const float*)d_in[24];
    const float* bl_follower = (const float*)d_in[25];
    const int* posts_u = (const int*)d_in[26];
    const int* posts_n = (const int*)d_in[27];
    const int* pub_s = (const int*)d_in[28];
    const int* pub_n = (const int*)d_in[29];
    const int* fol_f = (const int*)d_in[30];
    const int* fol_u = (const int*)d_in[31];
    float* out = (float*)d_out;

    float *bufA, *bufB, *agg, *deg;
    int *cnt, *cur, *rp, *el;
    cudaGetSymbolAddress((void**)&bufA, g_bufA);
    cudaGetSymbolAddress((void**)&bufB, g_bufB);
    cudaGetSymbolAddress((void**)&agg, g_agg);
    cudaGetSymbolAddress((void**)&deg, g_deg);
    cudaGetSymbolAddress((void**)&cnt, g_cnt);
    cudaGetSymbolAddress((void**)&cur, g_cur);
    cudaGetSymbolAddress((void**)&rp, g_rp);
    cudaGetSymbolAddress((void**)&el, g_el);

    cudaFuncSetAttribute(tgemm_kernel, cudaFuncAttributeMaxDynamicSharedMemorySize, SM_BYTES);

    auto gemm1 = [](const float* A, int lda, const float* W, int K, const float* b,
                    float* C, int M, float scale, int act) {
        tgemm_kernel<<<(M + 127) / 128, 256, SM_BYTES>>>(A, lda, W, nullptr, K, K, b, nullptr,
                                                         C, M, scale, act);
    };
    auto gemm2 = [](const float* A, const float* Wa, const float* Wb, const float* ba,
                    const float* bb, float* C, int M, float scale) {
        tgemm_kernel<<<(M + 127) / 128, 256, SM_BYTES>>>(A, 256, Wa, Wb, 128, 256, ba, bb,
                                                         C, M, scale, 1);
    };

    const size_t HH = (size_t)HDIM * HDIM;

    // ---- dense layer 1 (launch idx 0-3): x -> bufA ----
    gemm1(x_user, 128, Wi1_user, 128, bi1_user, bufA + OFF_U, N_USER, 1.f, 1);
    gemm1(x_source, 128, Wi1_source, 128, bi1_source, bufA + OFF_S, N_SOURCE, 1.f, 1);
    gemm1(x_follower, 128, Wi1_follower, 128, bi1_follower, bufA + OFF_F, N_FOLLOWER, 1.f, 1);
    gemm1(x_news, 300, Wi1_news, 300, bi1_news, bufA + OFF_N, N_NEWS, 1.f, 1);

    // ---- dense layer 2 (idx 4-7; idx 5 = follower M=200k for ncu capture) ----
    gemm1(bufA + OFF_U, 128, Wi2 + 0 * HH, 128, bi2 + 0 * HDIM, bufB + OFF_U, N_USER, 1.f, 1);
    gemm1(bufA + OFF_F, 128, Wi2 + 3 * HH, 128, bi2 + 3 * HDIM, bufB + OFF_F, N_FOLLOWER, 1.f, 1);
    gemm1(bufA + OFF_N, 128, Wi2 + 1 * HH, 128, bi2 + 1 * HDIM, bufB + OFF_N, N_NEWS, 1.f, 1);
    gemm1(bufA + OFF_S, 128, Wi2 + 2 * HH, 128, bi2 + 2 * HDIM, bufB + OFF_S, N_SOURCE, 1.f, 1);

    // ---- CSR build ----
    zero4_kernel<<<2048, 256>>>((float4*)cnt, DEG_TOTAL / 4);
    zero4_kernel<<<2048, 256>>>((float4*)cur, DEG_TOTAL / 4);
    counti_kernel<<<2048, 256>>>(posts_u, E_POSTS, cnt + DS_POSTS_U);
    counti_kernel<<<2048, 256>>>(posts_n, E_POSTS, cnt + DS_POSTS_N);
    counti_kernel<<<512, 256>>>(pub_s, E_PUB, cnt + DS_PUB_S);
    counti_kernel<<<512, 256>>>(pub_n, E_PUB, cnt + DS_PUB_N);
    counti_kernel<<<4096, 256>>>(fol_f, E_FOL, cnt + DS_FOL_F);
    counti_kernel<<<4096, 256>>>(fol_u, E_FOL, cnt + DS_FOL_U);
    rsqrt_cnt_kernel<<<2048, 256>>>(cnt, deg, DEG_TOTAL);
    scan6_kernel<<<6, 1024>>>(cnt, rp);
    fill_kernel<<<2048, 256>>>(posts_u, posts_n, E_POSTS, rp + RP0, cur + DS_POSTS_N, el + EL0);
    fill_kernel<<<2048, 256>>>(posts_n, posts_u, E_POSTS, rp + RP1, cur + DS_POSTS_U, el + EL1);
    fill_kernel<<<512, 256>>>(pub_s, pub_n, E_PUB, rp + RP2, cur + DS_PUB_N, el + EL2);
    fill_kernel<<<512, 256>>>(pub_n, pub_s, E_PUB, rp + RP3, cur + DS_PUB_S, el + EL3);
    fill_kernel<<<4096, 256>>>(fol_f, fol_u, E_FOL, rp + RP4, cur + DS_FOL_U, el + EL4);
    fill_kernel<<<4096, 256>>>(fol_u, fol_f, E_FOL, rp + RP5, cur + DS_FOL_F, el + EL5);

    auto gath = [&](const float* hbase, size_t hoff, int rpo, int elo, int rs_src, int rs_dst,
                    int colofs, int n_dst) {
        gather_kernel<<<(n_dst + 7) / 8, 256>>>(hbase + hoff, rp + rpo, el + elo,
                                                deg + rs_src, deg + rs_dst, agg, colofs, n_dst);
    };

    // ---- conv layers ----
    const size_t H1_BASE = (size_t)TOT_NODES * 2;
    float* h1_u = out + H1_BASE + OFF_U;
    float* h1_n = out + H1_BASE + OFF_N;
    float* h1_s = out + H1_BASE + OFF_S;
    float* h1_f = out + H1_BASE + OFF_F;

    for (int layer = 0; layer < 2; layer++) {
        const float* hsrc = (layer == 0) ? bufB : bufA;
        const float* Wc = (layer == 0) ? conv1_W : conv2_W;
        const float* bc = (layer == 0) ? conv1_b : conv2_b;
        float* o_u = (layer == 0) ? bufA + OFF_U : h1_u;
        float* o_n = (layer == 0) ? bufA + OFF_N : h1_n;
        float* o_s = (layer == 0) ? bufA + OFF_S : h1_s;
        float* o_f = (layer == 0) ? bufA + OFF_F : h1_f;

        // user: r1 (news->user) cols 0-127, r4 (follower->user) cols 128-255
        gath(hsrc, OFF_N, RP1, EL1, DS_POSTS_N, DS_POSTS_U, 0, N_USER);
        gath(hsrc, OFF_F, RP4, EL4, DS_FOL_F, DS_FOL_U, 128, N_USER);
        gemm2(agg, Wc + (0 * 6 + 1) * HH, Wc + (0 * 6 + 4) * HH,
              bc + (0 * 6 + 1) * HDIM, bc + (0 * 6 + 4) * HDIM, o_u, N_USER, 0.5f);
        // news: r0 (user->news) cols 0-127, r2 (source->news) cols 128-255
        gath(hsrc, OFF_U, RP0, EL0, DS_POSTS_U, DS_POSTS_N, 0, N_NEWS);
        gath(hsrc, OFF_S, RP2, EL2, DS_PUB_S, DS_PUB_N, 128, N_NEWS);
        gemm2(agg, Wc + (1 * 6 + 0) * HH, Wc + (1 * 6 + 2) * HH,
              bc + (1 * 6 + 0) * HDIM, bc + (1 * 6 + 2) * HDIM, o_n, N_NEWS, 0.5f);
        // source: r3 (news->source), single relation
        gath(hsrc, OFF_N, RP3, EL3, DS_PUB_N, DS_PUB_S, 0, N_SOURCE);
        tgemm_kernel<<<(N_SOURCE + 127) / 128, 256, SM_BYTES>>>(
            agg, 256, Wc + (2 * 6 + 3) * HH, nullptr, 128, 128,
            bc + (2 * 6 + 3) * HDIM, nullptr, o_s, N_SOURCE, 1.f, 1);
        // follower: r5 (user->follower), single relation
        gath(hsrc, OFF_U, RP5, EL5, DS_FOL_U, DS_FOL_F, 0, N_FOLLOWER);
        tgemm_kernel<<<(N_FOLLOWER + 127) / 128, 256, SM_BYTES>>>(
            agg, 256, Wc + (3 * 6 + 5) * HH, nullptr, 128, 128,
            bc + (3 * 6 + 5) * HDIM, nullptr, o_f, N_FOLLOWER, 1.f, 1);
    }

    // ---- head ----
    float* out_u = out + 0;
    float* out_n = out + (size_t)N_USER * 2;
    float* out_s = out + (size_t)(N_USER + N_NEWS) * 2;
    float* out_f = out + (size_t)(N_USER + N_NEWS + N_SOURCE) * 2;
    head_kernel<<<(N_USER * 32 + 255) / 256, 256>>>(h1_u, Wl_user, bl_user, out_u, N_USER);
    head_kernel<<<(N_NEWS * 32 + 255) / 256, 256>>>(h1_n, Wl_news, bl_news, out_n, N_NEWS);
    head_kernel<<<(N_SOURCE * 32 + 255) / 256, 256>>>(h1_s, Wl_source, bl_source, out_s, N_SOURCE);
    head_kernel<<<(N_FOLLOWER * 32 + 255) / 256, 256>>>(h1_f, Wl_follower, bl_follower, out_f, N_FOLLOWER);
}